// round 3
// baseline (speedup 1.0000x reference)
#include <cuda_runtime.h>

// Problem constants
#define BNUM 8
#define NPTS 8192
#define CIN  64
#define COUT 128
#define KNB  16
#define MK   16
#define NPOINTS (BNUM * NPTS)   // 65536
#define TP   16                 // points per block
#define NBLOCKS (NPOINTS / TP)  // 4096
#define OUT_ELEMS ((size_t)NPOINTS * COUT)  // 8388608
#define PTS_ELEMS (NPOINTS * 3)             // 196608

// Shared memory layout (floats):
//  s_A[3][32]            96
//  s_beff[32]            32
//  s_l2w[16][32]        512
//  s_l2b[16]             16
//  s_l3w[16][16]        256
//  s_l3b[16]             16
//  s_bias[128]          128
//  s_wk[16][16][17]    4352   (pad 17 to kill STS bank conflicts)
//  s_f [16][16][64]   16384   (reused as s_agg[16][1024] m-major after Phase B)
#define SMEM_FLOATS (96 + 32 + 512 + 16 + 256 + 16 + 128 + 4352 + 16384)
#define SMEM_BYTES  (SMEM_FLOATS * 4)       // ~85 KB -> 2 CTAs/SM

__global__ void __launch_bounds__(256, 2) ptconv_kernel(
    const float* __restrict__ features,    // [B,N,64]
    const float* __restrict__ input_pts,   // [B,N,3]
    const float* __restrict__ output_pts,  // [B,N,3]
    const int*   __restrict__ indices,     // [B,N,16]
    const float* __restrict__ centers,     // [3,16]
    const float* __restrict__ weight,      // [64,16,128]
    const float* __restrict__ bias,        // [128]
    const float* __restrict__ l1w,         // [32,48]
    const float* __restrict__ l1b,         // [32]
    const float* __restrict__ l2w,         // [16,32]
    const float* __restrict__ l2b,         // [16]
    const float* __restrict__ l3w,         // [16,16]
    const float* __restrict__ l3b,         // [16]
    float* __restrict__ out)               // [B,N,128]
{
    extern __shared__ float sm[];
    float* s_A    = sm;                 // [3][32]
    float* s_beff = s_A + 96;           // [32]
    float* s_l2w  = s_beff + 32;        // [16][32]
    float* s_l2b  = s_l2w + 512;        // [16]
    float* s_l3w  = s_l2b + 16;         // [16][16]
    float* s_l3b  = s_l3w + 256;        // [16]
    float* s_bias = s_l3b + 16;         // [128]
    float* s_wk   = s_bias + 128;       // [16][16][17]
    float* s_f    = s_wk + 16*16*17;    // [16][16][64], later s_agg[16][1024]
    float* s_agg  = s_f;                // alias (reuse after Phase B)

    const int tid = threadIdx.x;

    // ---------------- Init: fold centers + l1 into affine form, stage weights ----------------
    if (tid < 32) {
        const int o = tid;
        float be = l1b[o];
        float a[3];
        #pragma unroll
        for (int j = 0; j < 3; j++) {
            float as = 0.f;
            #pragma unroll
            for (int m = 0; m < 16; m++) {
                float wv = l1w[o * 48 + j * 16 + m];
                be -= centers[j * 16 + m] * wv;
                as += wv;
            }
            a[j] = as;
        }
        s_A[0 * 32 + o] = a[0];
        s_A[1 * 32 + o] = a[1];
        s_A[2 * 32 + o] = a[2];
        s_beff[o] = be;
    }
    for (int i = tid; i < 512; i += 256) s_l2w[i] = l2w[i];
    if (tid < 256) s_l3w[tid] = l3w[tid];
    if (tid < 16)  s_l2b[tid] = l2b[tid];
    if (tid < 16)  s_l3b[tid] = l3b[tid];
    if (tid < 128) s_bias[tid] = bias[tid];
    __syncthreads();

    // ---------------- Phase A1: per-(point,neighbor) MLP -> s_wk ----------------
    {
        const int p  = tid >> 4;
        const int k  = tid & 15;
        const int pi = blockIdx.x * TP + p;        // flat point index = b*N + n
        const int b  = pi >> 13;                   // N = 8192

        const int idx = indices[pi * 16 + k];
        const int src = (b << 13) + idx;

        const float q0 = input_pts[src * 3 + 0] - output_pts[pi * 3 + 0];
        const float q1 = input_pts[src * 3 + 1] - output_pts[pi * 3 + 1];
        const float q2 = input_pts[src * 3 + 2] - output_pts[pi * 3 + 2];

        float h1[32];
        #pragma unroll
        for (int o = 0; o < 32; o++) {
            float v = s_beff[o] + s_A[o] * q0 + s_A[32 + o] * q1 + s_A[64 + o] * q2;
            h1[o] = fmaxf(v, 0.f);
        }
        float h2[16];
        #pragma unroll
        for (int m = 0; m < 16; m++) {
            float acc = s_l2b[m];
            #pragma unroll
            for (int j = 0; j < 32; j++) acc += h1[j] * s_l2w[m * 32 + j];
            h2[m] = fmaxf(acc, 0.f);
        }
        #pragma unroll
        for (int m = 0; m < 16; m++) {
            float acc = s_l3b[m];
            #pragma unroll
            for (int j = 0; j < 16; j++) acc += h2[j] * s_l3w[m * 16 + j];
            s_wk[(p * 16 + k) * 17 + m] = fmaxf(acc, 0.f);
        }
    }

    // ---------------- Phase A2: coalesced feature gather -> s_f ----------------
    {
        const float4* fsrc = reinterpret_cast<const float4*>(features);
        float4* fdst = reinterpret_cast<float4*>(s_f);
        #pragma unroll
        for (int u = tid; u < TP * KNB * 16; u += 256) {   // 4096 float4 units
            const int pp  = u >> 8;
            const int kk  = (u >> 4) & 15;
            const int c4  = u & 15;
            const int ppi = blockIdx.x * TP + pp;
            const int idx = indices[ppi * 16 + kk];
            const int src = ((ppi >> 13) << 13) + idx;
            fdst[(pp * 16 + kk) * 16 + c4] = fsrc[src * 16 + c4];
        }
    }
    __syncthreads();

    // ---------------- Phase B: agg[p][m*64+c] = sum_k f[p][k][c] * wk[p][k][m] ----------------
    // Accumulate in registers, then (after a sync) overwrite s_f with the result.
    {
        const int pb = tid >> 4;
        const int c0 = (tid & 15) * 4;
        float acc[16][4];
        #pragma unroll
        for (int m = 0; m < 16; m++) {
            #pragma unroll
            for (int cc = 0; cc < 4; cc++) acc[m][cc] = 0.f;
        }
        #pragma unroll
        for (int kk = 0; kk < 16; kk++) {
            float4 f4 = *reinterpret_cast<const float4*>(&s_f[(pb * 16 + kk) * 64 + c0]);
            const float* wkrow = &s_wk[(pb * 16 + kk) * 17];
            #pragma unroll
            for (int m = 0; m < 16; m++) {
                const float w = wkrow[m];
                acc[m][0] += f4.x * w;
                acc[m][1] += f4.y * w;
                acc[m][2] += f4.z * w;
                acc[m][3] += f4.w * w;
            }
        }
        __syncthreads();   // all Phase-B reads of s_f done -> safe to overwrite
        #pragma unroll
        for (int m = 0; m < 16; m++) {
            float4 st = make_float4(acc[m][0], acc[m][1], acc[m][2], acc[m][3]);
            *reinterpret_cast<float4*>(&s_agg[pb * 1024 + m * 64 + c0]) = st;
        }
    }
    __syncthreads();

    // ---------------- Phase C: out[p][co] = (1/16) * sum_{c,m} agg[p][c,m] * W[c,m,co] + bias ----------------
    {
        const int co = tid & 127;
        const int p0 = (tid >> 7) * 8;   // half the block handles 8 points
        float acc[8];
        #pragma unroll
        for (int i = 0; i < 8; i++) acc[i] = 0.f;

        #pragma unroll
        for (int m = 0; m < 16; m++) {
            const float* agg0 = &s_agg[p0 * 1024 + m * 64];
            const float* wcol = &weight[m * 128 + co];
            #pragma unroll 4
            for (int c4 = 0; c4 < 16; c4++) {
                const int c = c4 * 4;
                const float w0 = wcol[(c + 0) * 2048];
                const float w1 = wcol[(c + 1) * 2048];
                const float w2 = wcol[(c + 2) * 2048];
                const float w3 = wcol[(c + 3) * 2048];
                #pragma unroll
                for (int pp = 0; pp < 8; pp++) {
                    float4 a = *reinterpret_cast<const float4*>(&agg0[pp * 1024 + c]);
                    acc[pp] += a.x * w0;
                    acc[pp] += a.y * w1;
                    acc[pp] += a.z * w2;
                    acc[pp] += a.w * w3;
                }
            }
        }

        const float inv = 1.f / 16.f;
        const float bv = s_bias[co];
        #pragma unroll
        for (int pp = 0; pp < 8; pp++) {
            const int ppi = blockIdx.x * TP + p0 + pp;
            out[(size_t)ppi * 128 + co] = acc[pp] * inv + bv;
        }
    }
}

// Second output of the tuple: output_pts passthrough.
__global__ void copy_pts_kernel(const float* __restrict__ src, float* __restrict__ dst)
{
    const int i = blockIdx.x * blockDim.x + threadIdx.x;
    if (i < PTS_ELEMS) dst[i] = src[i];
}

extern "C" void kernel_launch(void* const* d_in, const int* in_sizes, int n_in,
                              void* d_out, int out_size)
{
    const float* features   = (const float*)d_in[0];
    const float* input_pts  = (const float*)d_in[1];
    const float* output_pts = (const float*)d_in[2];
    const int*   indices    = (const int*)d_in[3];
    const float* centers    = (const float*)d_in[4];
    const float* weight     = (const float*)d_in[5];
    const float* bias       = (const float*)d_in[6];
    const float* l1w        = (const float*)d_in[7];
    const float* l1b        = (const float*)d_in[8];
    const float* l2w        = (const float*)d_in[9];
    const float* l2b        = (const float*)d_in[10];
    const float* l3w        = (const float*)d_in[11];
    const float* l3b        = (const float*)d_in[12];
    float* out = (float*)d_out;

    cudaFuncSetAttribute(ptconv_kernel, cudaFuncAttributeMaxDynamicSharedMemorySize, SMEM_BYTES);

    ptconv_kernel<<<NBLOCKS, 256, SMEM_BYTES>>>(
        features, input_pts, output_pts, indices, centers, weight, bias,
        l1w, l1b, l2w, l2b, l3w, l3b, out);

    copy_pts_kernel<<<(PTS_ELEMS + 255) / 256, 256>>>(output_pts, out + OUT_ELEMS);
}

// round 5
// speedup vs baseline: 2.4093x; 2.4093x over previous
#include <cuda_runtime.h>
#include <cuda_bf16.h>
#include <cstdint>

// Problem constants
#define BNUM 8
#define NPTS 8192
#define NPOINTS (BNUM * NPTS)   // 65536
#define TP   16                 // points per block
#define NBLOCKS (NPOINTS / TP)  // 4096
#define OUT_ELEMS ((size_t)NPOINTS * 128)
#define PTS_ELEMS (NPOINTS * 3)

// bf16 A staging in smem: per point-row 512 k-pairs (u32) + 1 pad word per 8
// + 4 extra so row stride == 580 words == 4 (mod 32)  -> conflict-free frags
#define RSW 580

// Shared memory layout (floats):
//  s_A[3][32]            96
//  s_beff[32]            32
//  s_l2w[16][32]        512
//  s_l2b[16]             16
//  s_l3w[16][16]        256
//  s_l3b[16]             16
//  s_bias[128]          128
//  s_wk[16][16][17]    4352
//  s_ab region        18560   (Phase A2/B: s_f fp32 features 16384;
//                              then reused as s_ahi/s_alo bf16 pair arrays 2*16*580 u32)
#define AB_OFF (96 + 32 + 512 + 16 + 256 + 16 + 128 + 4352)   // 5408
#define SMEM_FLOATS (AB_OFF + 18560)
#define SMEM_BYTES  (SMEM_FLOATS * 4)    // 95872 B -> 2 CTAs/SM

// Pre-split weight in mma fragment layout: [kt(64)][nt(16)][lane(32)][half(2)] u32
__device__ uint32_t g_whi[65536];
__device__ uint32_t g_wlo[65536];

static __device__ __forceinline__ uint32_t pack2(float x0, float x1) {
    __nv_bfloat162 h = __floats2bfloat162_rn(x0, x1);   // .x = x0 (low half)
    return *reinterpret_cast<uint32_t*>(&h);
}

static __device__ __forceinline__ void mma16816(
    float& d0, float& d1, float& d2, float& d3,
    uint32_t a0, uint32_t a1, uint32_t a2, uint32_t a3,
    uint32_t b0, uint32_t b1)
{
    asm volatile(
        "mma.sync.aligned.m16n8k16.row.col.f32.bf16.bf16.f32 "
        "{%0,%1,%2,%3}, {%4,%5,%6,%7}, {%8,%9}, {%0,%1,%2,%3};"
        : "+f"(d0), "+f"(d1), "+f"(d2), "+f"(d3)
        : "r"(a0), "r"(a1), "r"(a2), "r"(a3), "r"(b0), "r"(b1));
}

// ---------------- weight prep: fp32 [1024][128] -> hi/lo bf16 fragment layout ----------------
__global__ void prep_weight_kernel(const float* __restrict__ w)
{
    int i = blockIdx.x * blockDim.x + threadIdx.x;    // (kt, nt, lane)
    if (i >= 64 * 16 * 32) return;
    const int lane = i & 31;
    const int nt   = (i >> 5) & 15;
    const int kt   = i >> 9;
    const int tk   = lane & 3;
    const int g    = lane >> 2;
    const int n    = nt * 8 + g;
    #pragma unroll
    for (int half = 0; half < 2; half++) {
        const int k0 = kt * 16 + half * 8 + tk * 2;
        const float w0 = w[k0 * 128 + n];
        const float w1 = w[(k0 + 1) * 128 + n];
        const __nv_bfloat16 h0 = __float2bfloat16(w0);
        const __nv_bfloat16 h1 = __float2bfloat16(w1);
        const float l0 = w0 - __bfloat162float(h0);
        const float l1 = w1 - __bfloat162float(h1);
        const int idx = ((kt * 16 + nt) * 32 + lane) * 2 + half;
        g_whi[idx] = pack2(w0, w1);
        g_wlo[idx] = pack2(l0, l1);
    }
}

__global__ void __launch_bounds__(256, 2) ptconv_kernel(
    const float* __restrict__ features,    // [B,N,64]
    const float* __restrict__ input_pts,   // [B,N,3]
    const float* __restrict__ output_pts,  // [B,N,3]
    const int*   __restrict__ indices,     // [B,N,16]
    const float* __restrict__ centers,     // [3,16]
    const float* __restrict__ bias,        // [128]
    const float* __restrict__ l1w,         // [32,48]
    const float* __restrict__ l1b,         // [32]
    const float* __restrict__ l2w,         // [16,32]
    const float* __restrict__ l2b,         // [16]
    const float* __restrict__ l3w,         // [16,16]
    const float* __restrict__ l3b,         // [16]
    float* __restrict__ out)               // [B,N,128]
{
    extern __shared__ float sm[];
    float* s_A    = sm;                 // [3][32]
    float* s_beff = s_A + 96;           // [32]
    float* s_l2w  = s_beff + 32;        // [16][32]
    float* s_l2b  = s_l2w + 512;        // [16]
    float* s_l3w  = s_l2b + 16;         // [16][16]
    float* s_l3b  = s_l3w + 256;        // [16]
    float* s_bias = s_l3b + 16;         // [128]
    float* s_wk   = s_bias + 128;       // [16][16][17]
    float* s_f    = sm + AB_OFF;        // fp32 features [16][16][64] (phase A2/B)
    uint32_t* s_ahiW = (uint32_t*)(sm + AB_OFF);        // bf16 hi pairs [16][RSW]
    uint32_t* s_aloW = s_ahiW + 16 * RSW;               // bf16 lo pairs [16][RSW]

    const int tid = threadIdx.x;

    // ---------------- Init: fold centers + l1 into affine form, stage weights ----------------
    if (tid < 32) {
        const int o = tid;
        float be = l1b[o];
        float a[3];
        #pragma unroll
        for (int j = 0; j < 3; j++) {
            float as = 0.f;
            #pragma unroll
            for (int m = 0; m < 16; m++) {
                float wv = l1w[o * 48 + j * 16 + m];
                be -= centers[j * 16 + m] * wv;
                as += wv;
            }
            a[j] = as;
        }
        s_A[0 * 32 + o] = a[0];
        s_A[1 * 32 + o] = a[1];
        s_A[2 * 32 + o] = a[2];
        s_beff[o] = be;
    }
    for (int i = tid; i < 512; i += 256) s_l2w[i] = l2w[i];
    if (tid < 256) s_l3w[tid] = l3w[tid];
    if (tid < 16)  s_l2b[tid] = l2b[tid];
    if (tid < 16)  s_l3b[tid] = l3b[tid];
    if (tid < 128) s_bias[tid] = bias[tid];
    __syncthreads();

    // ---------------- Phase A1: per-(point,neighbor) MLP -> s_wk ----------------
    {
        const int p  = tid >> 4;
        const int k  = tid & 15;
        const int pi = blockIdx.x * TP + p;
        const int b  = pi >> 13;                   // N = 8192

        const int idx = indices[pi * 16 + k];
        const int src = (b << 13) + idx;

        const float q0 = input_pts[src * 3 + 0] - output_pts[pi * 3 + 0];
        const float q1 = input_pts[src * 3 + 1] - output_pts[pi * 3 + 1];
        const float q2 = input_pts[src * 3 + 2] - output_pts[pi * 3 + 2];

        float h1[32];
        #pragma unroll
        for (int o = 0; o < 32; o++) {
            float v = s_beff[o] + s_A[o] * q0 + s_A[32 + o] * q1 + s_A[64 + o] * q2;
            h1[o] = fmaxf(v, 0.f);
        }
        float h2[16];
        #pragma unroll
        for (int m = 0; m < 16; m++) {
            float acc = s_l2b[m];
            #pragma unroll
            for (int j = 0; j < 32; j++) acc += h1[j] * s_l2w[m * 32 + j];
            h2[m] = fmaxf(acc, 0.f);
        }
        #pragma unroll
        for (int m = 0; m < 16; m++) {
            float acc = s_l3b[m];
            #pragma unroll
            for (int j = 0; j < 16; j++) acc += h2[j] * s_l3w[m * 16 + j];
            s_wk[(p * 16 + k) * 17 + m] = fmaxf(acc, 0.f);
        }
    }

    // ---------------- Phase A2: coalesced feature gather -> s_f ----------------
    {
        const float4* fsrc = reinterpret_cast<const float4*>(features);
        float4* fdst = reinterpret_cast<float4*>(s_f);
        #pragma unroll
        for (int u = tid; u < TP * 16 * 16; u += 256) {   // 4096 float4 units
            const int pp  = u >> 8;
            const int kk  = (u >> 4) & 15;
            const int c4  = u & 15;
            const int ppi = blockIdx.x * TP + pp;
            const int idx = indices[ppi * 16 + kk];
            const int src = ((ppi >> 13) << 13) + idx;
            fdst[(pp * 16 + kk) * 16 + c4] = fsrc[src * 16 + c4];
        }
    }
    __syncthreads();

    // ---------------- Phase B: A[p][k=c*16+m] = sum_kk f[p][kk][c] * wk[p][kk][m] ----------------
    // Thread (pb, ci) owns c in {ci, ci+16, ci+32, ci+48}; accumulate in regs,
    // then (post-sync) store hi/lo bf16 k-pairs into padded smem arrays.
    {
        const int pb = tid >> 4;
        const int ci = tid & 15;
        float acc[16][4];
        #pragma unroll
        for (int m = 0; m < 16; m++) {
            #pragma unroll
            for (int cc = 0; cc < 4; cc++) acc[m][cc] = 0.f;
        }
        #pragma unroll
        for (int kk = 0; kk < 16; kk++) {
            const float* frow = &s_f[(pb * 16 + kk) * 64];
            float fv[4];
            #pragma unroll
            for (int cc = 0; cc < 4; cc++) fv[cc] = frow[ci + 16 * cc];
            const float* wkrow = &s_wk[(pb * 16 + kk) * 17];
            #pragma unroll
            for (int m = 0; m < 16; m++) {
                const float w = wkrow[m];
                #pragma unroll
                for (int cc = 0; cc < 4; cc++) acc[m][cc] += fv[cc] * w;
            }
        }
        __syncthreads();   // all Phase-B reads of s_f done -> safe to overwrite region
        #pragma unroll
        for (int cc = 0; cc < 4; cc++) {
            const int c = ci + 16 * cc;
            const int base = pb * RSW + 9 * c;   // word(kp) = kp + kp/8 = 9c + mp
            #pragma unroll
            for (int mp = 0; mp < 8; mp++) {
                const float x0 = acc[2 * mp][cc];
                const float x1 = acc[2 * mp + 1][cc];
                const __nv_bfloat162 h = __floats2bfloat162_rn(x0, x1);
                const float l0 = x0 - __bfloat162float(h.x);
                const float l1 = x1 - __bfloat162float(h.y);
                s_ahiW[base + mp] = *reinterpret_cast<const uint32_t*>(&h);
                s_aloW[base + mp] = pack2(l0, l1);
            }
        }
    }
    __syncthreads();

    // ---------------- Phase C: tensor-core GEMM  out[16x128] = A[16x1024] @ W[1024x128] ----------------
    // 8 warps x 2 n-tiles(n8) x 64 k-tiles(k16) x 3 split-mmas, fp32 accum.
    {
        const int lane = tid & 31;
        const int warp = tid >> 5;
        const int tk = lane & 3;
        const int g  = lane >> 2;
        const int nt0 = warp * 2, nt1 = nt0 + 1;

        const uint2* __restrict__ bhi = reinterpret_cast<const uint2*>(g_whi);
        const uint2* __restrict__ blo = reinterpret_cast<const uint2*>(g_wlo);

        float d0[4] = {0.f, 0.f, 0.f, 0.f};
        float d1[4] = {0.f, 0.f, 0.f, 0.f};

        const int aoff0 = g * RSW + tk;
        const int aoff1 = (g + 8) * RSW + tk;

        #pragma unroll 4
        for (int kt = 0; kt < 64; kt++) {
            const int ab = kt * 9;
            const uint32_t ah0 = s_ahiW[aoff0 + ab];
            const uint32_t ah1 = s_ahiW[aoff1 + ab];
            const uint32_t ah2 = s_ahiW[aoff0 + ab + 4];
            const uint32_t ah3 = s_ahiW[aoff1 + ab + 4];
            const uint32_t al0 = s_aloW[aoff0 + ab];
            const uint32_t al1 = s_aloW[aoff1 + ab];
            const uint32_t al2 = s_aloW[aoff0 + ab + 4];
            const uint32_t al3 = s_aloW[aoff1 + ab + 4];

            const int bbase = (kt * 16) * 32 + lane;
            const uint2 bh0 = bhi[bbase + nt0 * 32];
            const uint2 bh1 = bhi[bbase + nt1 * 32];
            const uint2 bl0 = blo[bbase + nt0 * 32];
            const uint2 bl1 = blo[bbase + nt1 * 32];

            mma16816(d0[0], d0[1], d0[2], d0[3], ah0, ah1, ah2, ah3, bh0.x, bh0.y);
            mma16816(d0[0], d0[1], d0[2], d0[3], ah0, ah1, ah2, ah3, bl0.x, bl0.y);
            mma16816(d0[0], d0[1], d0[2], d0[3], al0, al1, al2, al3, bh0.x, bh0.y);

            mma16816(d1[0], d1[1], d1[2], d1[3], ah0, ah1, ah2, ah3, bh1.x, bh1.y);
            mma16816(d1[0], d1[1], d1[2], d1[3], ah0, ah1, ah2, ah3, bl1.x, bl1.y);
            mma16816(d1[0], d1[1], d1[2], d1[3], al0, al1, al2, al3, bh1.x, bh1.y);
        }

        const float inv = 1.f / 16.f;
        const int pibase = blockIdx.x * TP;

        const int col0 = nt0 * 8 + tk * 2;
        const float b00 = s_bias[col0], b01 = s_bias[col0 + 1];
        *reinterpret_cast<float2*>(&out[(size_t)(pibase + g) * 128 + col0]) =
            make_float2(d0[0] * inv + b00, d0[1] * inv + b01);
        *reinterpret_cast<float2*>(&out[(size_t)(pibase + g + 8) * 128 + col0]) =
            make_float2(d0[2] * inv + b00, d0[3] * inv + b01);

        const int col1 = nt1 * 8 + tk * 2;
        const float b10 = s_bias[col1], b11 = s_bias[col1 + 1];
        *reinterpret_cast<float2*>(&out[(size_t)(pibase + g) * 128 + col1]) =
            make_float2(d1[0] * inv + b10, d1[1] * inv + b11);
        *reinterpret_cast<float2*>(&out[(size_t)(pibase + g + 8) * 128 + col1]) =
            make_float2(d1[2] * inv + b10, d1[3] * inv + b11);
    }
}

// Second output of the tuple: output_pts passthrough.
__global__ void copy_pts_kernel(const float* __restrict__ src, float* __restrict__ dst)
{
    const int i = blockIdx.x * blockDim.x + threadIdx.x;
    if (i < PTS_ELEMS) dst[i] = src[i];
}

extern "C" void kernel_launch(void* const* d_in, const int* in_sizes, int n_in,
                              void* d_out, int out_size)
{
    const float* features   = (const float*)d_in[0];
    const float* input_pts  = (const float*)d_in[1];
    const float* output_pts = (const float*)d_in[2];
    const int*   indices    = (const int*)d_in[3];
    const float* centers    = (const float*)d_in[4];
    const float* weight     = (const float*)d_in[5];
    const float* bias       = (const float*)d_in[6];
    const float* l1w        = (const float*)d_in[7];
    const float* l1b        = (const float*)d_in[8];
    const float* l2w        = (const float*)d_in[9];
    const float* l2b        = (const float*)d_in[10];
    const float* l3w        = (const float*)d_in[11];
    const float* l3b        = (const float*)d_in[12];
    float* out = (float*)d_out;

    cudaFuncSetAttribute(ptconv_kernel, cudaFuncAttributeMaxDynamicSharedMemorySize, SMEM_BYTES);

    // copy first so the ncu -s 5 capture lands on the main kernel (launch order: c,p,m | c,p,m -> #6 = main)
    copy_pts_kernel<<<(PTS_ELEMS + 255) / 256, 256>>>(output_pts, out + OUT_ELEMS);

    prep_weight_kernel<<<(64 * 16 * 32 + 255) / 256, 256>>>(weight);

    ptconv_kernel<<<NBLOCKS, 256, SMEM_BYTES>>>(
        features, input_pts, output_pts, indices, centers, bias,
        l1w, l1b, l2w, l2b, l3w, l3b, out);
}